// round 1
// baseline (speedup 1.0000x reference)
#include <cuda_runtime.h>
#include <cstddef>

// Butterfly_25220047962207: out = butterfly_multiply(twiddle, x) + bias
// n=1024, log_n=10, nstacks=nblocks=1, increasing_stride, 32768 rows.
//
// Design: 256 threads/block. Thread k owns pair indices {k, k+256} at EVERY
// stage, so its 2*10*4 = 80 twiddle floats are loaded ONCE per block into
// registers (coalesced float4) and amortized over all rows the block handles.
// Between stage stride s and 2s, each pair exchanges exactly ONE value with
// pair (index xor s):
//   s in {1,2,4,8,16}  -> __shfl_xor_sync           (in-warp)
//   s in {32,64,128}   -> tiny smem exchange (512 floats per transition)
//   s == 256           -> thread-local swap (its own two pairs are partners)
// Stage 0 (s=1) reads pairs directly from global as float2 (adjacent
// elements -> coalesced), stage 9 (s=512) yields elements k, k+256, k+512,
// k+768 -> coalesced stores. Bias in registers. Grid-stride over rows with
// next-row prefetch.

constexpr int TPB   = 256;
constexpr int GRID  = 296;   // ~2 blocks/SM * 148 SMs; keeps twiddle L2 traffic ~24MB

__global__ __launch_bounds__(TPB, 2)
void butterfly_kernel(const float* __restrict__ x,
                      const float* __restrict__ tw,
                      const float* __restrict__ bias,
                      float* __restrict__ out,
                      int nrows)
{
    __shared__ float buf[3][512];
    const int k = threadIdx.x;

    // ---- twiddle into registers: float4 (t00,t01,t10,t11) per (stage, pair)
    const float4* tw4 = reinterpret_cast<const float4*>(tw);
    float4 ta[10], tb[10];
#pragma unroll
    for (int j = 0; j < 10; ++j) {
        ta[j] = tw4[j * 512 + k];
        tb[j] = tw4[j * 512 + 256 + k];
    }
    const float bias0 = bias[k];
    const float bias1 = bias[k + 256];
    const float bias2 = bias[k + 512];
    const float bias3 = bias[k + 768];

    const float2* x2 = reinterpret_cast<const float2*>(x);

    int row = blockIdx.x;
    float2 ina = make_float2(0.f, 0.f), inb = make_float2(0.f, 0.f);
    if (row < nrows) {
        ina = x2[(size_t)row * 512 + k];
        inb = x2[(size_t)row * 512 + 256 + k];
    }

    while (row < nrows) {
        // prefetch next row before computing the current one
        const int nrow = row + GRID;
        float2 na = make_float2(0.f, 0.f), nb = make_float2(0.f, 0.f);
        if (nrow < nrows) {
            na = x2[(size_t)nrow * 512 + k];
            nb = x2[(size_t)nrow * 512 + 256 + k];
        }

        float xa0 = ina.x, xa1 = ina.y;   // pair a = index k
        float xb0 = inb.x, xb1 = inb.y;   // pair b = index k + 256

        float ya0, ya1, yb0, yb1;
#pragma unroll
        for (int j = 0; j < 10; ++j) {
            // 2x2 rotation: y0 = t00*x0 + t01*x1 ; y1 = t10*x0 + t11*x1
            ya0 = fmaf(ta[j].y, xa1, ta[j].x * xa0);
            ya1 = fmaf(ta[j].w, xa1, ta[j].z * xa0);
            yb0 = fmaf(tb[j].y, xb1, tb[j].x * xb0);
            yb1 = fmaf(tb[j].w, xb1, tb[j].z * xb0);

            if (j < 9) {
                const int d = 1 << j;
                // bit j of pair index (same for both owned pairs when j<8):
                const bool hi = (k & d) != 0;
                if (j <= 4) {
                    // in-warp exchange
                    float sa = hi ? ya0 : ya1;
                    float sb = hi ? yb0 : yb1;
                    float ra = __shfl_xor_sync(0xffffffffu, sa, d);
                    float rb = __shfl_xor_sync(0xffffffffu, sb, d);
                    xa0 = hi ? ra  : ya0;
                    xa1 = hi ? ya1 : ra;
                    xb0 = hi ? rb  : yb0;
                    xb1 = hi ? yb1 : rb;
                } else if (j <= 7) {
                    // cross-warp exchange through smem (distinct buffer per
                    // transition; reuse across rows is ordered by the later syncs)
                    float* B = buf[j - 5];
                    B[k]       = hi ? ya0 : ya1;
                    B[256 + k] = hi ? yb0 : yb1;
                    __syncthreads();
                    float ra = B[k ^ d];
                    float rb = B[256 + (k ^ d)];
                    xa0 = hi ? ra  : ya0;
                    xa1 = hi ? ya1 : ra;
                    xb0 = hi ? rb  : yb0;
                    xb1 = hi ? yb1 : rb;
                } else {
                    // j == 8, d == 256: partner pair is this thread's other pair
                    xa0 = ya0; xa1 = yb0;
                    xb0 = ya1; xb1 = yb1;
                }
            }
        }

        // after s=512: pair a holds elements (k, k+512), pair b (k+256, k+768)
        float* o = out + (size_t)row * 1024;
        o[k]        = ya0 + bias0;
        o[k + 256]  = yb0 + bias1;
        o[k + 512]  = ya1 + bias2;
        o[k + 768]  = yb1 + bias3;

        row = nrow;
        ina = na; inb = nb;
    }
}

extern "C" void kernel_launch(void* const* d_in, const int* in_sizes, int n_in,
                              void* d_out, int out_size)
{
    // identify inputs by element count: x=32768*1024, twiddle=10*512*4=20480, bias=1024
    const float* x  = nullptr;
    const float* tw = nullptr;
    const float* bs = nullptr;
    long long x_elems = 0;
    for (int i = 0; i < n_in; ++i) {
        if (in_sizes[i] == 20480)       tw = (const float*)d_in[i];
        else if (in_sizes[i] == 1024)   bs = (const float*)d_in[i];
        else { x = (const float*)d_in[i]; x_elems = in_sizes[i]; }
    }
    const int nrows = (int)(x_elems / 1024);

    butterfly_kernel<<<GRID, TPB>>>(x, tw, bs, (float*)d_out, nrows);
}

// round 2
// speedup vs baseline: 1.4444x; 1.4444x over previous
#include <cuda_runtime.h>
#include <cstddef>

// Butterfly n=1024, log_n=10, increasing stride, + bias. 32768 rows.
//
// Thread k (of 256) owns pair indices {k, k+256} at every stage; its 80
// twiddle floats load once per block. KEY CHANGE vs R1: exchange steering is
// baked into the twiddles at load time (row-swap for hi_j=(k>>j)&1, col-swap
// for sigma_j=(k>>(j-1))&1), so the steady-state loop has ZERO select
// instructions: compute (keep,send), shfl_xor/smem-exchange the send slot,
// received value lands directly in the next stage's input slot.
// Second change: 2 rows processed per iteration (independent chains to hide
// shfl/smem latency; barriers amortized to 1.5/row).

constexpr int TPB  = 256;
constexpr int GRID = 296;

__global__ __launch_bounds__(TPB, 2)
void butterfly_kernel(const float* __restrict__ x,
                      const float* __restrict__ tw,
                      const float* __restrict__ bias,
                      float* __restrict__ out,
                      int nrows)
{
    __shared__ float buf[3][1024];
    const int k = threadIdx.x;

    // ---- twiddles, pre-permuted per thread --------------------------------
    const float4* tw4 = reinterpret_cast<const float4*>(tw);
    float4 Ua[10], Ub[10];
#pragma unroll
    for (int j = 0; j < 10; ++j) {
        float4 t = tw4[j * 512 + k];
        float4 u = tw4[j * 512 + 256 + k];
        const bool rsw = (j <= 7) && (((k >> j) & 1) != 0);        // row swap (keep/send)
        const bool csw = (j >= 1) && (((k >> (j - 1)) & 1) != 0);  // col swap (input orient)
        if (rsw) { t = make_float4(t.z, t.w, t.x, t.y); u = make_float4(u.z, u.w, u.x, u.y); }
        if (csw) { t = make_float4(t.y, t.x, t.w, t.z); u = make_float4(u.y, u.x, u.w, u.z); }
        Ua[j] = t; Ub[j] = u;
    }
    const float bias0 = bias[k];
    const float bias1 = bias[k + 256];
    const float bias2 = bias[k + 512];
    const float bias3 = bias[k + 768];

    const float2* x2 = reinterpret_cast<const float2*>(x);
    const int npairs = (nrows + 1) >> 1;

    int pi = blockIdx.x;
    float2 A0 = make_float2(0.f, 0.f), B0 = A0, A1 = A0, B1 = A0;
    if (pi < npairs) {
        const int r0 = 2 * pi, r1 = 2 * pi + 1;
        A0 = x2[(size_t)r0 * 512 + k];
        B0 = x2[(size_t)r0 * 512 + 256 + k];
        if (r1 < nrows) {
            A1 = x2[(size_t)r1 * 512 + k];
            B1 = x2[(size_t)r1 * 512 + 256 + k];
        }
    }

    while (pi < npairs) {
        const int npi = pi + GRID;
        float2 NA0 = make_float2(0.f, 0.f), NB0 = NA0, NA1 = NA0, NB1 = NA0;
        if (npi < npairs) {                      // prefetch next pair of rows
            const int r0 = 2 * npi, r1 = 2 * npi + 1;
            NA0 = x2[(size_t)r0 * 512 + k];
            NB0 = x2[(size_t)r0 * 512 + 256 + k];
            if (r1 < nrows) {
                NA1 = x2[(size_t)r1 * 512 + k];
                NB1 = x2[(size_t)r1 * 512 + 256 + k];
            }
        }

        // register slots: p = "slot0", q = "slot1" (orientation folded into twiddles)
        float pa0 = A0.x, qa0 = A0.y, pb0 = B0.x, qb0 = B0.y;   // row 0
        float pa1 = A1.x, qa1 = A1.y, pb1 = B1.x, qb1 = B1.y;   // row 1

#pragma unroll
        for (int j = 0; j < 8; ++j) {
            const int d = 1 << j;
            // compute (keep -> p, send -> b) for all 4 pairs; zero selects
            float ba0, bb0, ba1, bb1, a;
            a   = fmaf(Ua[j].y, qa0, Ua[j].x * pa0);
            ba0 = fmaf(Ua[j].w, qa0, Ua[j].z * pa0);  pa0 = a;
            a   = fmaf(Ub[j].y, qb0, Ub[j].x * pb0);
            bb0 = fmaf(Ub[j].w, qb0, Ub[j].z * pb0);  pb0 = a;
            a   = fmaf(Ua[j].y, qa1, Ua[j].x * pa1);
            ba1 = fmaf(Ua[j].w, qa1, Ua[j].z * pa1);  pa1 = a;
            a   = fmaf(Ub[j].y, qb1, Ub[j].x * pb1);
            bb1 = fmaf(Ub[j].w, qb1, Ub[j].z * pb1);  pb1 = a;

            if (j <= 4) {
                qa0 = __shfl_xor_sync(0xffffffffu, ba0, d);
                qb0 = __shfl_xor_sync(0xffffffffu, bb0, d);
                qa1 = __shfl_xor_sync(0xffffffffu, ba1, d);
                qb1 = __shfl_xor_sync(0xffffffffu, bb1, d);
            } else {
                float* B = buf[j - 5];
                B[k]       = ba0;
                B[256 + k] = bb0;
                B[512 + k] = ba1;
                B[768 + k] = bb1;
                __syncthreads();
                const int kx = k ^ d;
                qa0 = B[kx];
                qb0 = B[256 + kx];
                qa1 = B[512 + kx];
                qb1 = B[768 + kx];
            }
        }

        // stage 8 (d=256): both partners are this thread's own pairs (local)
        float ya0_0 = fmaf(Ua[8].y, qa0, Ua[8].x * pa0);
        float ya1_0 = fmaf(Ua[8].w, qa0, Ua[8].z * pa0);
        float yb0_0 = fmaf(Ub[8].y, qb0, Ub[8].x * pb0);
        float yb1_0 = fmaf(Ub[8].w, qb0, Ub[8].z * pb0);
        float ya0_1 = fmaf(Ua[8].y, qa1, Ua[8].x * pa1);
        float ya1_1 = fmaf(Ua[8].w, qa1, Ua[8].z * pa1);
        float yb0_1 = fmaf(Ub[8].y, qb1, Ub[8].x * pb1);
        float yb1_1 = fmaf(Ub[8].w, qb1, Ub[8].z * pb1);

        // stage 9 (d=512): pair a inputs (ya0, yb0), pair b inputs (ya1, yb1)
        float za0_0 = fmaf(Ua[9].y, yb0_0, Ua[9].x * ya0_0);
        float za1_0 = fmaf(Ua[9].w, yb0_0, Ua[9].z * ya0_0);
        float zb0_0 = fmaf(Ub[9].y, yb1_0, Ub[9].x * ya1_0);
        float zb1_0 = fmaf(Ub[9].w, yb1_0, Ub[9].z * ya1_0);
        float za0_1 = fmaf(Ua[9].y, yb0_1, Ua[9].x * ya0_1);
        float za1_1 = fmaf(Ua[9].w, yb0_1, Ua[9].z * ya0_1);
        float zb0_1 = fmaf(Ub[9].y, yb1_1, Ub[9].x * ya1_1);
        float zb1_1 = fmaf(Ub[9].w, yb1_1, Ub[9].z * ya1_1);

        // outputs: za0->k, zb0->k+256, za1->k+512, zb1->k+768
        const int r0 = 2 * pi, r1 = 2 * pi + 1;
        {
            float* o = out + (size_t)r0 * 1024;
            o[k]       = za0_0 + bias0;
            o[k + 256] = zb0_0 + bias1;
            o[k + 512] = za1_0 + bias2;
            o[k + 768] = zb1_0 + bias3;
        }
        if (r1 < nrows) {
            float* o = out + (size_t)r1 * 1024;
            o[k]       = za0_1 + bias0;
            o[k + 256] = zb0_1 + bias1;
            o[k + 512] = za1_1 + bias2;
            o[k + 768] = zb1_1 + bias3;
        }

        pi = npi;
        A0 = NA0; B0 = NB0; A1 = NA1; B1 = NB1;
    }
}

extern "C" void kernel_launch(void* const* d_in, const int* in_sizes, int n_in,
                              void* d_out, int out_size)
{
    const float* x  = nullptr;
    const float* tw = nullptr;
    const float* bs = nullptr;
    long long x_elems = 0;
    for (int i = 0; i < n_in; ++i) {
        if (in_sizes[i] == 20480)     tw = (const float*)d_in[i];
        else if (in_sizes[i] == 1024) bs = (const float*)d_in[i];
        else { x = (const float*)d_in[i]; x_elems = in_sizes[i]; }
    }
    const int nrows = (int)(x_elems / 1024);

    butterfly_kernel<<<GRID, TPB>>>(x, tw, bs, (float*)d_out, nrows);
}